// round 6
// baseline (speedup 1.0000x reference)
#include <cuda_runtime.h>

#define TSTEPS 20
#define NROWS  32768
#define DEMB   64
#define DH     128
#define DOUT   5
#define GATES  512   // 4*DH
#define KTOT   192   // DEMB + DH
#define MTILE  32

// Packed-duplicate A layout: per k-row, 4 row-groups of 8 float2 (64B) + 32B pad
// = 96 floats (384B) per k. Group stride 24 floats keeps the four LDS.128
// addresses per instruction on disjoint bank quads ({0,96,64,32} mod 128).
#define KSTRIDE 96   // floats per k-row
#define GSTRIDE 24   // floats per row-group
#define AS2_BYTES (KTOT * KSTRIDE * 4)   // 73728 B

// Persistent recurrent state (allowed scratch: __device__ globals)
__device__ float g_h[(size_t)NROWS * DH];
__device__ float g_c[(size_t)NROWS * DH];
__device__ int   g_mask_is_i32;   // 1 if mask stored as int32, 0 if 1-byte

// ---- packed f32x2 helpers (B300 FFMA2 fast path, PTX-only) ----
__device__ __forceinline__ unsigned long long pk2(float lo, float hi) {
    unsigned long long r;
    asm("mov.b64 %0, {%1, %2};" : "=l"(r) : "f"(lo), "f"(hi));
    return r;
}
__device__ __forceinline__ unsigned long long ffma2(unsigned long long a,
                                                    unsigned long long b,
                                                    unsigned long long c) {
    unsigned long long d;
    asm("fma.rn.f32x2 %0, %1, %2, %3;" : "=l"(d) : "l"(a), "l"(b), "l"(c));
    return d;
}
__device__ __forceinline__ float2 up2(unsigned long long v) {
    float lo, hi;
    asm("mov.b64 {%0, %1}, %2;" : "=f"(lo), "=f"(hi) : "l"(v));
    return make_float2(lo, hi);
}

__device__ __forceinline__ float sigf(float x) {
    return 1.0f / (1.0f + __expf(-x));
}
__device__ __forceinline__ float tanhf_fast(float x) {
    x = fminf(fmaxf(x, -30.0f), 30.0f);
    float e = __expf(-2.0f * x);
    return (1.0f - e) / (1.0f + e);
}

// Detect mask element width (int32 vs 1-byte). Reads first 4KB — safe in both
// interpretations (buffer >= T*N bytes minimum).
__global__ void detect_mask_kernel(const unsigned char* __restrict__ m) {
    if (threadIdx.x == 0 && blockIdx.x == 0) {
        int is_i32 = 1;
        for (int i = 0; i < 4096; ++i) {
            if ((i & 3) != 0 && m[i] != 0) { is_i32 = 0; break; }
        }
        g_mask_is_i32 = is_i32;
    }
}

__global__ void init_state(const float* __restrict__ h0, const float* __restrict__ c0) {
    int i = blockIdx.x * blockDim.x + threadIdx.x;
    ((float4*)g_h)[i] = ((const float4*)h0)[i];
    ((float4*)g_c)[i] = ((const float4*)c0)[i];
}

__device__ __forceinline__ int as2_idx(int k, int row) {
    return k * KSTRIDE + (row >> 3) * GSTRIDE + (row & 7) * 2;
}

__global__ __launch_bounds__(256, 2)
void lstm_step(const float* __restrict__ nodes_t,          // [N,2] slice for step t
               const unsigned char* __restrict__ mask_base,// full mask buffer
               int tstep,
               const float* __restrict__ W_embed, const float* __restrict__ b_embed,
               const float* __restrict__ W_ih,    const float* __restrict__ b_ih,
               const float* __restrict__ W_hh,    const float* __restrict__ b_hh,
               const float* __restrict__ W_out,   const float* __restrict__ b_out,
               float* __restrict__ out_t,                  // [N,5] slice for step t
               float* __restrict__ h_fin, float* __restrict__ c_fin,
               int is_last)
{
    extern __shared__ float As2[];             // [KTOT][KSTRIDE] packed (a,a) pairs
    __shared__ float outbuf[MTILE][DOUT];      // per-row output-projection reduction
    __shared__ unsigned char mask_s[MTILE];

    const int tid  = threadIdx.x;
    const int warp = tid >> 5;
    const int lane = tid & 31;
    const int row0 = blockIdx.x * MTILE;

    if (tid < MTILE) {
        const size_t ms = g_mask_is_i32 ? 4u : 1u;   // bytes per mask element
        mask_s[tid] = mask_base[((size_t)tstep * NROWS + row0 + tid) * ms];
    }
    if (tid < MTILE * DOUT) ((float*)outbuf)[tid] = 0.0f;

    // ---- stage embedding (duplicated pairs): warp w covers k in [8w, 8w+8), row = lane
    {
        float2 x = *(const float2*)(nodes_t + (size_t)(row0 + lane) * 2);
        #pragma unroll
        for (int j = 0; j < 8; ++j) {
            int k = warp * 8 + j;
            float e = fmaf(x.x, W_embed[k], fmaf(x.y, W_embed[DEMB + k], b_embed[k]));
            e = fmaxf(e, 0.0f);
            *(float2*)&As2[as2_idx(k, lane)] = make_float2(e, e);
        }
    }
    // ---- stage h (duplicated pairs): warp w covers k in [16w, 16w+16), row = lane
    {
        const float* hrow = g_h + (size_t)(row0 + lane) * DH + warp * 16;
        #pragma unroll
        for (int jj = 0; jj < 4; ++jj) {
            float4 hv = *(const float4*)(hrow + jj * 4);
            int kb = DEMB + warp * 16 + jj * 4;
            *(float2*)&As2[as2_idx(kb + 0, lane)] = make_float2(hv.x, hv.x);
            *(float2*)&As2[as2_idx(kb + 1, lane)] = make_float2(hv.y, hv.y);
            *(float2*)&As2[as2_idx(kb + 2, lane)] = make_float2(hv.z, hv.z);
            *(float2*)&As2[as2_idx(kb + 3, lane)] = make_float2(hv.w, hv.w);
        }
    }
    __syncthreads();

    // ---- thread tile: 8 rows (rbase..rbase+7) x 8 cols = dims {d0,d0+1} x 4 gates
    const int cgid  = lane & 7;
    const int grp   = lane >> 3;      // row group, rbase = grp*8
    const int rbase = grp * 8;
    const int d0    = warp * 16 + cgid * 2;

    unsigned long long acc[8][4];
    #pragma unroll
    for (int g = 0; g < 4; ++g) {
        float2 bi = *(const float2*)(b_ih + d0 + 128 * g);
        float2 bh = *(const float2*)(b_hh + d0 + 128 * g);
        unsigned long long b2 = pk2(bi.x + bh.x, bi.y + bh.y);
        #pragma unroll
        for (int r = 0; r < 8; ++r) acc[r][g] = b2;
    }

    // ---- main K loop, segment 1: emb @ W_ih  (k = 0..63)
    {
        const float* wp = W_ih + d0;
        #pragma unroll 4
        for (int k = 0; k < DEMB; ++k) {
            unsigned long long w2[4];
            #pragma unroll
            for (int g = 0; g < 4; ++g)
                w2[g] = *(const unsigned long long*)(wp + (size_t)k * GATES + 128 * g);
            const ulonglong2* ap = (const ulonglong2*)&As2[k * KSTRIDE + grp * GSTRIDE];
            unsigned long long a2[8];
            #pragma unroll
            for (int j = 0; j < 4; ++j) {
                ulonglong2 v = ap[j];
                a2[2 * j] = v.x; a2[2 * j + 1] = v.y;
            }
            #pragma unroll
            for (int r = 0; r < 8; ++r)
                #pragma unroll
                for (int g = 0; g < 4; ++g) acc[r][g] = ffma2(a2[r], w2[g], acc[r][g]);
        }
    }
    // ---- main K loop, segment 2: h @ W_hh  (k = 0..127)
    {
        const float* wp = W_hh + d0;
        #pragma unroll 4
        for (int k = 0; k < DH; ++k) {
            unsigned long long w2[4];
            #pragma unroll
            for (int g = 0; g < 4; ++g)
                w2[g] = *(const unsigned long long*)(wp + (size_t)k * GATES + 128 * g);
            const ulonglong2* ap = (const ulonglong2*)&As2[(DEMB + k) * KSTRIDE + grp * GSTRIDE];
            unsigned long long a2[8];
            #pragma unroll
            for (int j = 0; j < 4; ++j) {
                ulonglong2 v = ap[j];
                a2[2 * j] = v.x; a2[2 * j + 1] = v.y;
            }
            #pragma unroll
            for (int r = 0; r < 8; ++r)
                #pragma unroll
                for (int g = 0; g < 4; ++g) acc[r][g] = ffma2(a2[r], w2[g], acc[r][g]);
        }
    }

    // ---- LSTM epilogue: thread owns dims {d0,d0+1} with all four gates for its 8 rows
    const bool last = (is_last != 0);
    #pragma unroll
    for (int r = 0; r < 8; ++r) {
        const int srow = rbase + r;
        const int row  = row0 + srow;
        const bool m   = (mask_s[srow] != 0);

        float2 iv = up2(acc[r][0]);
        float2 fv = up2(acc[r][1]);
        float2 gv = up2(acc[r][2]);
        float2 ov = up2(acc[r][3]);
        float2 co = *(const float2*)(g_c + (size_t)row * DH + d0);

        float ivs[2] = {iv.x, iv.y}, fvs[2] = {fv.x, fv.y};
        float gvs[2] = {gv.x, gv.y}, ovs[2] = {ov.x, ov.y};
        float cold[2] = {co.x, co.y};
        float cn[2], hn[2];
        #pragma unroll
        for (int dd = 0; dd < 2; ++dd) {
            float i_ = sigf(ivs[dd]);
            float f_ = sigf(fvs[dd]);
            float o_ = sigf(ovs[dd]);
            float g_ = tanhf_fast(gvs[dd]);
            cn[dd] = f_ * cold[dd] + i_ * g_;
            hn[dd] = o_ * tanhf_fast(cn[dd]);
        }

        if (m) {
            #pragma unroll
            for (int q = 0; q < DOUT; ++q) {
                float p = fmaf(hn[0], W_out[(size_t)d0 * DOUT + q],
                               hn[1] * W_out[(size_t)(d0 + 1) * DOUT + q]);
                atomicAdd(&outbuf[srow][q], p);
            }
            if (!last) {
                *(float2*)(g_h + (size_t)row * DH + d0) = make_float2(hn[0], hn[1]);
                *(float2*)(g_c + (size_t)row * DH + d0) = make_float2(cn[0], cn[1]);
            }
        }
        if (last) {
            float h0o = As2[as2_idx(DEMB + d0, srow)];
            float h1o = As2[as2_idx(DEMB + d0 + 1, srow)];
            *(float2*)(h_fin + (size_t)row * DH + d0) =
                make_float2(m ? hn[0] : h0o, m ? hn[1] : h1o);
            *(float2*)(c_fin + (size_t)row * DH + d0) =
                make_float2(m ? cn[0] : cold[0], m ? cn[1] : cold[1]);
        }
    }

    __syncthreads();
    if (tid < MTILE * DOUT) {
        int r32 = tid / DOUT, q = tid % DOUT;
        float v = mask_s[r32] ? (outbuf[r32][q] + b_out[q]) : 0.0f;
        out_t[(size_t)(row0 + r32) * DOUT + q] = v;
    }
}

extern "C" void kernel_launch(void* const* d_in, const int* in_sizes, int n_in,
                              void* d_out, int out_size) {
    const float*         nodes   = (const float*)d_in[0];
    const unsigned char* mask    = (const unsigned char*)d_in[1];
    const float*         h0      = (const float*)d_in[2];
    const float*         c0      = (const float*)d_in[3];
    const float*         W_embed = (const float*)d_in[4];
    const float*         b_embed = (const float*)d_in[5];
    const float*         W_ih    = (const float*)d_in[6];
    const float*         b_ih    = (const float*)d_in[7];
    const float*         W_hh    = (const float*)d_in[8];
    const float*         b_hh    = (const float*)d_in[9];
    const float*         W_out   = (const float*)d_in[10];
    const float*         b_out   = (const float*)d_in[11];

    float* out   = (float*)d_out;
    float* h_fin = out + (size_t)TSTEPS * NROWS * DOUT;
    float* c_fin = h_fin + (size_t)NROWS * DH;

    static int smem_set = 0;
    if (!smem_set) {
        cudaFuncSetAttribute(lstm_step,
                             cudaFuncAttributeMaxDynamicSharedMemorySize, AS2_BYTES);
        smem_set = 1;
    }

    detect_mask_kernel<<<1, 32>>>(mask);
    init_state<<<(NROWS * DH / 4) / 256, 256>>>(h0, c0);
    for (int t = 0; t < TSTEPS; ++t) {
        lstm_step<<<NROWS / MTILE, 256, AS2_BYTES>>>(
            nodes + (size_t)t * NROWS * 2,
            mask, t,
            W_embed, b_embed, W_ih, b_ih, W_hh, b_hh, W_out, b_out,
            out + (size_t)t * NROWS * DOUT,
            h_fin, c_fin,
            (t == TSTEPS - 1) ? 1 : 0);
    }
}

// round 9
// speedup vs baseline: 2.1537x; 2.1537x over previous
#include <cuda_runtime.h>
#include <cuda_bf16.h>
#include <cstdint>

#define TSTEPS 20
#define NROWS  32768
#define DEMB   64
#define DH     128
#define DOUT   5
#define GATES  512   // 4*DH
#define KTOT   192   // DEMB + DH
#define MTILE  32
#define NCHUNK 12    // KTOT / 16

// Persistent recurrent state + split weights (allowed scratch: __device__ globals)
__device__ float g_h[(size_t)NROWS * DH];
__device__ float g_c[(size_t)NROWS * DH];
__device__ int   g_mask_is_i32;
// W^T split into bf16 hi/lo, layout [12 chunks][512 n][16 k] with XOR-16B swizzle:
// elem slot for (chunk,n,k): (chunk*512+n)*16 + (((k&8) ^ ((n&4)?8:0)) | (k&7))
__device__ __nv_bfloat16 g_wt_hi[NCHUNK * 512 * 16];
__device__ __nv_bfloat16 g_wt_lo[NCHUNK * 512 * 16];

// ---- smem layout (bytes) ----
#define OFF_WHI   0        // 16384  : W^T hi chunk [512][16] bf16 (swizzled)
#define OFF_WLO   16384    // 16384  : W^T lo chunk
#define OFF_AHI   32768    // 12800  : A hi [32 rows][200 bf16] (pitch 400B)
#define OFF_ALO   45568    // 12800  : A lo
#define OFF_HN    58368    // 16896  : h_new f32 [32][132]
#define OFF_WOUT  75264    // 2560   : W_out f32 [128][5]
#define OFF_MASK  77824    // 32
#define SMEM_BYTES 77888
#define APITCH_B  400      // bytes per A row (200 bf16)
#define APITCH_E  200      // bf16 per A row

__device__ __forceinline__ uint32_t smem_u32(const void* p) {
    uint32_t a;
    asm("{ .reg .u64 t; cvta.to.shared.u64 t, %1; cvt.u32.u64 %0, t; }" : "=r"(a) : "l"(p));
    return a;
}
__device__ __forceinline__ void ldsm_x4(uint32_t* r, uint32_t addr) {
    asm volatile("ldmatrix.sync.aligned.m8n8.x4.shared.b16 {%0,%1,%2,%3}, [%4];"
        : "=r"(r[0]), "=r"(r[1]), "=r"(r[2]), "=r"(r[3]) : "r"(addr));
}
__device__ __forceinline__ void ldsm_x2(uint32_t& r0, uint32_t& r1, uint32_t addr) {
    asm volatile("ldmatrix.sync.aligned.m8n8.x2.shared.b16 {%0,%1}, [%2];"
        : "=r"(r0), "=r"(r1) : "r"(addr));
}
__device__ __forceinline__ void mma16816(float* c, const uint32_t* a, uint32_t b0, uint32_t b1) {
    asm volatile("mma.sync.aligned.m16n8k16.row.col.f32.bf16.bf16.f32 "
        "{%0,%1,%2,%3}, {%4,%5,%6,%7}, {%8,%9}, {%0,%1,%2,%3};"
        : "+f"(c[0]), "+f"(c[1]), "+f"(c[2]), "+f"(c[3])
        : "r"(a[0]), "r"(a[1]), "r"(a[2]), "r"(a[3]), "r"(b0), "r"(b1));
}

__device__ __forceinline__ float sigf(float x) { return 1.0f / (1.0f + __expf(-x)); }
__device__ __forceinline__ float tanhf_fast(float x) {
    x = fminf(fmaxf(x, -30.0f), 30.0f);
    float e = __expf(-2.0f * x);
    return (1.0f - e) / (1.0f + e);
}

__global__ void detect_mask_kernel(const unsigned char* __restrict__ m) {
    if (threadIdx.x == 0 && blockIdx.x == 0) {
        int is_i32 = 1;
        for (int i = 0; i < 4096; ++i)
            if ((i & 3) != 0 && m[i] != 0) { is_i32 = 0; break; }
        g_mask_is_i32 = is_i32;
    }
}

__global__ void init_state(const float* __restrict__ h0, const float* __restrict__ c0) {
    int i = blockIdx.x * blockDim.x + threadIdx.x;
    ((float4*)g_h)[i] = ((const float4*)h0)[i];
    ((float4*)g_c)[i] = ((const float4*)c0)[i];
}

// Transpose + bf16-split weights into the pre-swizzled chunked layout.
__global__ void split_weights(const float* __restrict__ W_ih, const float* __restrict__ W_hh) {
    int idx = blockIdx.x * blockDim.x + threadIdx.x;   // 0 .. 98303
    int chunk = idx >> 13;            // /(512*16)
    int n     = (idx >> 4) & 511;
    int s     = idx & 15;             // swizzled within-row slot
    int k     = (s & 7) | ((s & 8) ^ ((n & 4) ? 8 : 0));
    int kg    = chunk * 16 + k;
    float w = (kg < DEMB) ? W_ih[(size_t)kg * GATES + n]
                          : W_hh[(size_t)(kg - DEMB) * GATES + n];
    __nv_bfloat16 hi = __float2bfloat16(w);
    __nv_bfloat16 lo = __float2bfloat16(w - __bfloat162float(hi));
    g_wt_hi[idx] = hi;
    g_wt_lo[idx] = lo;
}

__global__ __launch_bounds__(256, 2)
void lstm_step(const float* __restrict__ nodes_t,
               const unsigned char* __restrict__ mask_base, int tstep,
               const float* __restrict__ W_embed, const float* __restrict__ b_embed,
               const float* __restrict__ b_ih,    const float* __restrict__ b_hh,
               const float* __restrict__ W_out,   const float* __restrict__ b_out,
               float* __restrict__ out_t,
               float* __restrict__ h_fin, float* __restrict__ c_fin,
               int is_last)
{
    extern __shared__ char sm[];
    __nv_bfloat16* a_hi  = (__nv_bfloat16*)(sm + OFF_AHI);
    __nv_bfloat16* a_lo  = (__nv_bfloat16*)(sm + OFF_ALO);
    float*         hn_s  = (float*)(sm + OFF_HN);
    float*         wout_s= (float*)(sm + OFF_WOUT);
    unsigned char* mask_s= (unsigned char*)(sm + OFF_MASK);
    const uint32_t smb   = smem_u32(sm);

    const int tid  = threadIdx.x;
    const int warp = tid >> 5;
    const int lane = tid & 31;
    const int row0 = blockIdx.x * MTILE;

    if (tid < MTILE) {
        const size_t ms = g_mask_is_i32 ? 4u : 1u;
        mask_s[tid] = mask_base[((size_t)tstep * NROWS + row0 + tid) * ms];
    }
    // W_out -> smem (640 floats)
    for (int i = tid; i < DH * DOUT; i += 256) wout_s[i] = W_out[i];

    // ---- stage A = [relu(x@We+be) | h] as bf16 hi/lo, row-major pitch 200 elems
    {   // embedding: warp w covers k in [8w, 8w+8), row = lane
        float2 x = *(const float2*)(nodes_t + (size_t)(row0 + lane) * 2);
        #pragma unroll
        for (int j = 0; j < 8; ++j) {
            int k = warp * 8 + j;
            float e = fmaf(x.x, W_embed[k], fmaf(x.y, W_embed[DEMB + k], b_embed[k]));
            e = fmaxf(e, 0.0f);
            __nv_bfloat16 hi = __float2bfloat16(e);
            a_hi[lane * APITCH_E + k] = hi;
            a_lo[lane * APITCH_E + k] = __float2bfloat16(e - __bfloat162float(hi));
        }
        // h: warp w covers k in [64+16w, 64+16w+16), row = lane
        const float* hrow = g_h + (size_t)(row0 + lane) * DH + warp * 16;
        #pragma unroll
        for (int jj = 0; jj < 4; ++jj) {
            float4 hv = *(const float4*)(hrow + jj * 4);
            float vs[4] = {hv.x, hv.y, hv.z, hv.w};
            #pragma unroll
            for (int cc = 0; cc < 4; ++cc) {
                int k = DEMB + warp * 16 + jj * 4 + cc;
                __nv_bfloat16 hi = __float2bfloat16(vs[cc]);
                a_hi[lane * APITCH_E + k] = hi;
                a_lo[lane * APITCH_E + k] = __float2bfloat16(vs[cc] - __bfloat162float(hi));
            }
        }
    }

    // ---- accumulators: [mblk][nblk][gate][reg], init with biases
    float acc[2][2][4][4];
    #pragma unroll
    for (int nb = 0; nb < 2; ++nb)
        #pragma unroll
        for (int g = 0; g < 4; ++g) {
            int d   = 16 * warp + 8 * nb + 2 * (lane & 3);
            int off = 128 * g + d;
            float2 bi = *(const float2*)(b_ih + off);
            float2 bh = *(const float2*)(b_hh + off);
            float bx = bi.x + bh.x, by = bi.y + bh.y;
            #pragma unroll
            for (int mb = 0; mb < 2; ++mb) {
                acc[mb][nb][g][0] = bx; acc[mb][nb][g][1] = by;
                acc[mb][nb][g][2] = bx; acc[mb][nb][g][3] = by;
            }
        }

    // ---- GEMM mainloop over 12 k-chunks of 16
    const int arow = lane & 15;
    for (int c = 0; c < NCHUNK; ++c) {
        __syncthreads();   // prev-chunk consumers done; also covers A staging on c==0
        {   // cooperative load of this chunk's W^T hi/lo (16KB each)
            const uint4* srcH = (const uint4*)(g_wt_hi + (size_t)c * 8192);
            const uint4* srcL = (const uint4*)(g_wt_lo + (size_t)c * 8192);
            uint4* dstH = (uint4*)(sm + OFF_WHI);
            uint4* dstL = (uint4*)(sm + OFF_WLO);
            #pragma unroll
            for (int j = 0; j < 4; ++j) {
                dstH[tid + 256 * j] = srcH[tid + 256 * j];
                dstL[tid + 256 * j] = srcL[tid + 256 * j];
            }
        }
        __syncthreads();

        // A fragments for this chunk (both m-blocks, hi & lo)
        uint32_t ah[2][4], al[2][4];
        const int koff = c * 32 + ((lane & 16) ? 16 : 0);
        #pragma unroll
        for (int mb = 0; mb < 2; ++mb) {
            uint32_t ad = smb + OFF_AHI + (uint32_t)(mb * 16 + arow) * APITCH_B + koff;
            ldsm_x4(ah[mb], ad);
            ldsm_x4(al[mb], ad + (OFF_ALO - OFF_AHI));
        }

        #pragma unroll
        for (int g = 0; g < 4; ++g) {
            #pragma unroll
            for (int nb = 0; nb < 2; ++nb) {
                int nrow = 128 * g + 16 * warp + 8 * nb + (lane & 7);
                uint32_t kh = (lane & 8) ? 16u : 0u;
                uint32_t bd = smb + OFF_WHI + (uint32_t)nrow * 32
                            + (kh ^ ((nrow & 4) ? 16u : 0u));
                uint32_t bh0, bh1, bl0, bl1;
                ldsm_x2(bh0, bh1, bd);
                ldsm_x2(bl0, bl1, bd + 16384);
                #pragma unroll
                for (int mb = 0; mb < 2; ++mb) {
                    mma16816(acc[mb][nb][g], ah[mb], bh0, bh1);  // Ah@Wh
                    mma16816(acc[mb][nb][g], ah[mb], bl0, bl1);  // Ah@Wl
                    mma16816(acc[mb][nb][g], al[mb], bh0, bh1);  // Al@Wh
                }
            }
        }
    }

    // ---- LSTM epilogue: thread owns (row, dim-pair) with all 4 gates
    const bool last = (is_last != 0);
    #pragma unroll
    for (int mb = 0; mb < 2; ++mb)
        #pragma unroll
        for (int half = 0; half < 2; ++half) {
            int r    = mb * 16 + half * 8 + (lane >> 2);
            int grow = row0 + r;
            bool m   = (mask_s[r] != 0);
            #pragma unroll
            for (int nb = 0; nb < 2; ++nb) {
                int d = 16 * warp + 8 * nb + 2 * (lane & 3);
                float iv0 = acc[mb][nb][0][half * 2], iv1 = acc[mb][nb][0][half * 2 + 1];
                float fv0 = acc[mb][nb][1][half * 2], fv1 = acc[mb][nb][1][half * 2 + 1];
                float gv0 = acc[mb][nb][2][half * 2], gv1 = acc[mb][nb][2][half * 2 + 1];
                float ov0 = acc[mb][nb][3][half * 2], ov1 = acc[mb][nb][3][half * 2 + 1];
                float2 co = *(const float2*)(g_c + (size_t)grow * DH + d);

                float cn0 = sigf(fv0) * co.x + sigf(iv0) * tanhf_fast(gv0);
                float cn1 = sigf(fv1) * co.y + sigf(iv1) * tanhf_fast(gv1);
                float hn0 = sigf(ov0) * tanhf_fast(cn0);
                float hn1 = sigf(ov1) * tanhf_fast(cn1);

                hn_s[r * 132 + d]     = hn0;
                hn_s[r * 132 + d + 1] = hn1;

                if (!last) {
                    if (m) {
                        *(float2*)(g_h + (size_t)grow * DH + d) = make_float2(hn0, hn1);
                        *(float2*)(g_c + (size_t)grow * DH + d) = make_float2(cn0, cn1);
                    }
                } else {
                    float2 ho = *(const float2*)(g_h + (size_t)grow * DH + d);
                    *(float2*)(h_fin + (size_t)grow * DH + d) =
                        make_float2(m ? hn0 : ho.x, m ? hn1 : ho.y);
                    *(float2*)(c_fin + (size_t)grow * DH + d) =
                        make_float2(m ? cn0 : co.x, m ? cn1 : co.y);
                }
            }
        }

    // ---- output projection: out[r][q] = mask ? hn[r]@Wout[:,q] + b_out[q] : 0
    __syncthreads();
    if (tid < MTILE * DOUT) {
        int r = tid / DOUT, q = tid % DOUT;
        float a = b_out[q];
        const float* hr = hn_s + r * 132;
        #pragma unroll 8
        for (int d = 0; d < DH; ++d) a = fmaf(hr[d], wout_s[d * DOUT + q], a);
        out_t[(size_t)(row0 + r) * DOUT + q] = mask_s[r] ? a : 0.0f;
    }
}

extern "C" void kernel_launch(void* const* d_in, const int* in_sizes, int n_in,
                              void* d_out, int out_size) {
    const float*         nodes   = (const float*)d_in[0];
    const unsigned char* mask    = (const unsigned char*)d_in[1];
    const float*         h0      = (const float*)d_in[2];
    const float*         c0      = (const float*)d_in[3];
    const float*         W_embed = (const float*)d_in[4];
    const float*         b_embed = (const float*)d_in[5];
    const float*         W_ih    = (const float*)d_in[6];
    const float*         b_ih    = (const float*)d_in[7];
    const float*         W_hh    = (const float*)d_in[8];
    const float*         b_hh    = (const float*)d_in[9];
    const float*         W_out   = (const float*)d_in[10];
    const float*         b_out   = (const float*)d_in[11];

    float* out   = (float*)d_out;
    float* h_fin = out + (size_t)TSTEPS * NROWS * DOUT;
    float* c_fin = h_fin + (size_t)NROWS * DH;

    static int smem_set = 0;
    if (!smem_set) {
        cudaFuncSetAttribute(lstm_step,
                             cudaFuncAttributeMaxDynamicSharedMemorySize, SMEM_BYTES);
        smem_set = 1;
    }

    detect_mask_kernel<<<1, 32>>>(mask);
    init_state<<<(NROWS * DH / 4) / 256, 256>>>(h0, c0);
    split_weights<<<NCHUNK * 512 * 16 / 256, 256>>>(W_ih, W_hh);
    for (int t = 0; t < TSTEPS; ++t) {
        lstm_step<<<NROWS / MTILE, 256, SMEM_BYTES>>>(
            nodes + (size_t)t * NROWS * 2,
            mask, t,
            W_embed, b_embed, b_ih, b_hh, W_out, b_out,
            out + (size_t)t * NROWS * DOUT,
            h_fin, c_fin,
            (t == TSTEPS - 1) ? 1 : 0);
    }
}

// round 10
// speedup vs baseline: 3.0511x; 1.4167x over previous
#include <cuda_runtime.h>
#include <cuda_bf16.h>
#include <cstdint>

#define TSTEPS 20
#define NROWS  32768
#define DEMB   64
#define DH     128
#define DOUT   5
#define GATES  512   // 4*DH
#define KTOT   192   // DEMB + DH
#define MTILE  32
#define NCHUNK 12    // KTOT / 16

// Persistent recurrent state + split weights (allowed scratch: __device__ globals)
__device__ float g_h[(size_t)NROWS * DH];
__device__ float g_c[(size_t)NROWS * DH];
__device__ int   g_mask_is_i32;
// W^T split into bf16 hi/lo, layout [12 chunks][512 n][16 k] with XOR-16B swizzle:
// elem slot for (chunk,n,k): (chunk*512+n)*16 + (((k&8) ^ ((n&4)?8:0)) | (k&7))
__device__ __nv_bfloat16 g_wt_hi[NCHUNK * 512 * 16];
__device__ __nv_bfloat16 g_wt_lo[NCHUNK * 512 * 16];

// ---- smem layout (bytes) ----
// Double-buffered weight chunks: buffer b at 32768*b; hi at +0, lo at +16384.
#define WBUF_STRIDE 32768
#define OFF_AHI   65536    // 12800 : A hi [32 rows][200 bf16] (pitch 400B)
#define OFF_ALO   78336    // 12800 : A lo
#define OFF_HN    91136    // 16896 : h_new f32 [32][132]
#define OFF_WOUT  108032   // 2560  : W_out f32 [128][5]
#define OFF_MASK  110592   // 32
#define SMEM_BYTES 110624
#define APITCH_B  400      // bytes per A row (200 bf16)
#define APITCH_E  200      // bf16 per A row

__device__ __forceinline__ uint32_t smem_u32(const void* p) {
    uint32_t a;
    asm("{ .reg .u64 t; cvta.to.shared.u64 t, %1; cvt.u32.u64 %0, t; }" : "=r"(a) : "l"(p));
    return a;
}
__device__ __forceinline__ void ldsm_x4(uint32_t* r, uint32_t addr) {
    asm volatile("ldmatrix.sync.aligned.m8n8.x4.shared.b16 {%0,%1,%2,%3}, [%4];"
        : "=r"(r[0]), "=r"(r[1]), "=r"(r[2]), "=r"(r[3]) : "r"(addr));
}
__device__ __forceinline__ void mma16816(float* c, const uint32_t* a, uint32_t b0, uint32_t b1) {
    asm volatile("mma.sync.aligned.m16n8k16.row.col.f32.bf16.bf16.f32 "
        "{%0,%1,%2,%3}, {%4,%5,%6,%7}, {%8,%9}, {%0,%1,%2,%3};"
        : "+f"(c[0]), "+f"(c[1]), "+f"(c[2]), "+f"(c[3])
        : "r"(a[0]), "r"(a[1]), "r"(a[2]), "r"(a[3]), "r"(b0), "r"(b1));
}
__device__ __forceinline__ void cp_async16(uint32_t dst, const void* src) {
    asm volatile("cp.async.cg.shared.global [%0], [%1], 16;" :: "r"(dst), "l"(src));
}
__device__ __forceinline__ void cp_commit() {
    asm volatile("cp.async.commit_group;");
}
template <int N>
__device__ __forceinline__ void cp_wait() {
    asm volatile("cp.async.wait_group %0;" :: "n"(N));
}

__device__ __forceinline__ float sigf(float x) { return 1.0f / (1.0f + __expf(-x)); }
__device__ __forceinline__ float tanhf_fast(float x) {
    x = fminf(fmaxf(x, -30.0f), 30.0f);
    float e = __expf(-2.0f * x);
    return (1.0f - e) / (1.0f + e);
}

__global__ void detect_mask_kernel(const unsigned char* __restrict__ m) {
    if (threadIdx.x == 0 && blockIdx.x == 0) {
        int is_i32 = 1;
        for (int i = 0; i < 4096; ++i)
            if ((i & 3) != 0 && m[i] != 0) { is_i32 = 0; break; }
        g_mask_is_i32 = is_i32;
    }
}

__global__ void init_state(const float* __restrict__ h0, const float* __restrict__ c0) {
    int i = blockIdx.x * blockDim.x + threadIdx.x;
    ((float4*)g_h)[i] = ((const float4*)h0)[i];
    ((float4*)g_c)[i] = ((const float4*)c0)[i];
}

// Transpose + bf16-split weights into the pre-swizzled chunked layout.
__global__ void split_weights(const float* __restrict__ W_ih, const float* __restrict__ W_hh) {
    int idx = blockIdx.x * blockDim.x + threadIdx.x;   // 0 .. 98303
    int chunk = idx >> 13;            // /(512*16)
    int n     = (idx >> 4) & 511;
    int s     = idx & 15;             // swizzled within-row slot
    int k     = (s & 7) | ((s & 8) ^ ((n & 4) ? 8 : 0));
    int kg    = chunk * 16 + k;
    float w = (kg < DEMB) ? W_ih[(size_t)kg * GATES + n]
                          : W_hh[(size_t)(kg - DEMB) * GATES + n];
    __nv_bfloat16 hi = __float2bfloat16(w);
    __nv_bfloat16 lo = __float2bfloat16(w - __bfloat162float(hi));
    g_wt_hi[idx] = hi;
    g_wt_lo[idx] = lo;
}

__global__ __launch_bounds__(256, 2)
void lstm_step(const float* __restrict__ nodes_t,
               const unsigned char* __restrict__ mask_base, int tstep,
               const float* __restrict__ W_embed, const float* __restrict__ b_embed,
               const float* __restrict__ b_ih,    const float* __restrict__ b_hh,
               const float* __restrict__ W_out,   const float* __restrict__ b_out,
               float* __restrict__ out_t,
               float* __restrict__ h_fin, float* __restrict__ c_fin,
               int is_last)
{
    extern __shared__ char sm[];
    __nv_bfloat16* a_hi  = (__nv_bfloat16*)(sm + OFF_AHI);
    __nv_bfloat16* a_lo  = (__nv_bfloat16*)(sm + OFF_ALO);
    float*         hn_s  = (float*)(sm + OFF_HN);
    float*         wout_s= (float*)(sm + OFF_WOUT);
    unsigned char* mask_s= (unsigned char*)(sm + OFF_MASK);
    const uint32_t smb   = smem_u32(sm);

    const int tid  = threadIdx.x;
    const int warp = tid >> 5;
    const int lane = tid & 31;
    const int row0 = blockIdx.x * MTILE;

    // ---- kick off async load of weight chunk 0 immediately
    {
        uint32_t dst = smb + (uint32_t)(tid * 16);
        const char* srcH = (const char*)g_wt_hi + (size_t)tid * 16;
        const char* srcL = (const char*)g_wt_lo + (size_t)tid * 16;
        #pragma unroll
        for (int j = 0; j < 4; ++j) {
            cp_async16(dst + j * 4096,         srcH + j * 4096);
            cp_async16(dst + 16384 + j * 4096, srcL + j * 4096);
        }
        cp_commit();
    }

    if (tid < MTILE) {
        const size_t ms = g_mask_is_i32 ? 4u : 1u;
        mask_s[tid] = mask_base[((size_t)tstep * NROWS + row0 + tid) * ms];
    }
    for (int i = tid; i < DH * DOUT; i += 256) wout_s[i] = W_out[i];

    // ---- stage A = [relu(x@We+be) | h] as bf16 hi/lo, row-major pitch 200 elems
    {
        float2 x = *(const float2*)(nodes_t + (size_t)(row0 + lane) * 2);
        #pragma unroll
        for (int j = 0; j < 8; ++j) {
            int k = warp * 8 + j;
            float e = fmaf(x.x, W_embed[k], fmaf(x.y, W_embed[DEMB + k], b_embed[k]));
            e = fmaxf(e, 0.0f);
            __nv_bfloat16 hi = __float2bfloat16(e);
            a_hi[lane * APITCH_E + k] = hi;
            a_lo[lane * APITCH_E + k] = __float2bfloat16(e - __bfloat162float(hi));
        }
        const float* hrow = g_h + (size_t)(row0 + lane) * DH + warp * 16;
        #pragma unroll
        for (int jj = 0; jj < 4; ++jj) {
            float4 hv = *(const float4*)(hrow + jj * 4);
            float vs[4] = {hv.x, hv.y, hv.z, hv.w};
            #pragma unroll
            for (int cc = 0; cc < 4; ++cc) {
                int k = DEMB + warp * 16 + jj * 4 + cc;
                __nv_bfloat16 hi = __float2bfloat16(vs[cc]);
                a_hi[lane * APITCH_E + k] = hi;
                a_lo[lane * APITCH_E + k] = __float2bfloat16(vs[cc] - __bfloat162float(hi));
            }
        }
    }

    // ---- accumulators: [mblk][nblk][gate][reg], init with biases
    float acc[2][2][4][4];
    #pragma unroll
    for (int nb = 0; nb < 2; ++nb)
        #pragma unroll
        for (int g = 0; g < 4; ++g) {
            int d   = 16 * warp + 8 * nb + 2 * (lane & 3);
            int off = 128 * g + d;
            float2 bi = *(const float2*)(b_ih + off);
            float2 bh = *(const float2*)(b_hh + off);
            float bx = bi.x + bh.x, by = bi.y + bh.y;
            #pragma unroll
            for (int mb = 0; mb < 2; ++mb) {
                acc[mb][nb][g][0] = bx; acc[mb][nb][g][1] = by;
                acc[mb][nb][g][2] = bx; acc[mb][nb][g][3] = by;
            }
        }

    // ---- pipelined GEMM mainloop over 12 k-chunks of 16
    const int arow = lane & 15;
    // B fragment address: one ldmatrix.x4 covers both n-blocks x both k-halves.
    const int gidx  = (lane >> 3) & 3;        // 8-lane group
    const int bnb   = gidx >> 1;              // n-block for this group's addresses
    const int bkh   = (gidx & 1) * 16;        // k-half byte offset

    for (int c = 0; c < NCHUNK; ++c) {
        const int buf = c & 1;
        if (c + 1 < NCHUNK) {
            // prefetch chunk c+1 into the other buffer (freed at end of iter c-1)
            const int nb2 = (c + 1) & 1;
            uint32_t dst = smb + (uint32_t)(nb2 * WBUF_STRIDE + tid * 16);
            const char* srcH = (const char*)g_wt_hi + (size_t)(c + 1) * 16384 + (size_t)tid * 16;
            const char* srcL = (const char*)g_wt_lo + (size_t)(c + 1) * 16384 + (size_t)tid * 16;
            #pragma unroll
            for (int j = 0; j < 4; ++j) {
                cp_async16(dst + j * 4096,         srcH + j * 4096);
                cp_async16(dst + 16384 + j * 4096, srcL + j * 4096);
            }
            cp_commit();
            cp_wait<1>();   // chunk c resident (one group in flight: c+1)
        } else {
            cp_wait<0>();
        }
        __syncthreads();

        const uint32_t wb = smb + (uint32_t)(buf * WBUF_STRIDE);

        // A fragments for this chunk (both m-blocks, hi & lo)
        uint32_t ah[2][4], al[2][4];
        const int koff = c * 32 + ((lane & 16) ? 16 : 0);
        #pragma unroll
        for (int mb = 0; mb < 2; ++mb) {
            uint32_t ad = smb + OFF_AHI + (uint32_t)(mb * 16 + arow) * APITCH_B + koff;
            ldsm_x4(ah[mb], ad);
            ldsm_x4(al[mb], ad + (OFF_ALO - OFF_AHI));
        }

        #pragma unroll
        for (int g = 0; g < 4; ++g) {
            int nrow = 128 * g + 16 * warp + 8 * bnb + (lane & 7);
            uint32_t bd = wb + (uint32_t)nrow * 32
                        + ((uint32_t)bkh ^ ((nrow & 4) ? 16u : 0u));
            uint32_t bh[4], bl[4];
            ldsm_x4(bh, bd);            // bh[0..1]=nb0 frag, bh[2..3]=nb1 frag
            ldsm_x4(bl, bd + 16384);
            #pragma unroll
            for (int nb = 0; nb < 2; ++nb)
                #pragma unroll
                for (int mb = 0; mb < 2; ++mb) {
                    mma16816(acc[mb][nb][g], ah[mb], bh[2 * nb], bh[2 * nb + 1]); // Ah@Wh
                    mma16816(acc[mb][nb][g], ah[mb], bl[2 * nb], bl[2 * nb + 1]); // Ah@Wl
                    mma16816(acc[mb][nb][g], al[mb], bh[2 * nb], bh[2 * nb + 1]); // Al@Wh
                }
        }
        __syncthreads();   // all warps done with buf before it is overwritten
    }

    // ---- LSTM epilogue: thread owns (row, dim-pair) with all 4 gates
    const bool last = (is_last != 0);
    #pragma unroll
    for (int mb = 0; mb < 2; ++mb)
        #pragma unroll
        for (int half = 0; half < 2; ++half) {
            int r    = mb * 16 + half * 8 + (lane >> 2);
            int grow = row0 + r;
            bool m   = (mask_s[r] != 0);
            #pragma unroll
            for (int nb = 0; nb < 2; ++nb) {
                int d = 16 * warp + 8 * nb + 2 * (lane & 3);
                float iv0 = acc[mb][nb][0][half * 2], iv1 = acc[mb][nb][0][half * 2 + 1];
                float fv0 = acc[mb][nb][1][half * 2], fv1 = acc[mb][nb][1][half * 2 + 1];
                float gv0 = acc[mb][nb][2][half * 2], gv1 = acc[mb][nb][2][half * 2 + 1];
                float ov0 = acc[mb][nb][3][half * 2], ov1 = acc[mb][nb][3][half * 2 + 1];
                float2 co = *(const float2*)(g_c + (size_t)grow * DH + d);

                float cn0 = sigf(fv0) * co.x + sigf(iv0) * tanhf_fast(gv0);
                float cn1 = sigf(fv1) * co.y + sigf(iv1) * tanhf_fast(gv1);
                float hn0 = sigf(ov0) * tanhf_fast(cn0);
                float hn1 = sigf(ov1) * tanhf_fast(cn1);

                hn_s[r * 132 + d]     = hn0;
                hn_s[r * 132 + d + 1] = hn1;

                if (!last) {
                    if (m) {
                        *(float2*)(g_h + (size_t)grow * DH + d) = make_float2(hn0, hn1);
                        *(float2*)(g_c + (size_t)grow * DH + d) = make_float2(cn0, cn1);
                    }
                } else {
                    float2 ho = *(const float2*)(g_h + (size_t)grow * DH + d);
                    *(float2*)(h_fin + (size_t)grow * DH + d) =
                        make_float2(m ? hn0 : ho.x, m ? hn1 : ho.y);
                    *(float2*)(c_fin + (size_t)grow * DH + d) =
                        make_float2(m ? cn0 : co.x, m ? cn1 : co.y);
                }
            }
        }

    // ---- output projection: out[r][q] = mask ? hn[r]@Wout[:,q] + b_out[q] : 0
    __syncthreads();
    if (tid < MTILE * DOUT) {
        int r = tid / DOUT, q = tid % DOUT;
        float a = b_out[q];
        const float* hr = hn_s + r * 132;
        #pragma unroll 8
        for (int d = 0; d < DH; ++d) a = fmaf(hr[d], wout_s[d * DOUT + q], a);
        out_t[(size_t)(row0 + r) * DOUT + q] = mask_s[r] ? a : 0.0f;
    }
}

extern "C" void kernel_launch(void* const* d_in, const int* in_sizes, int n_in,
                              void* d_out, int out_size) {
    const float*         nodes   = (const float*)d_in[0];
    const unsigned char* mask    = (const unsigned char*)d_in[1];
    const float*         h0      = (const float*)d_in[2];
    const float*         c0      = (const float*)d_in[3];
    const float*         W_embed = (const float*)d_in[4];
    const float*         b_embed = (const float*)d_in[5];
    const float*         W_ih    = (const float*)d_in[6];
    const float*         b_ih    = (const float*)d_in[7];
    const float*         W_hh    = (const float*)d_in[8];
    const float*         b_hh    = (const float*)d_in[9];
    const float*         W_out   = (const float*)d_in[10];
    const float*         b_out   = (const float*)d_in[11];

    float* out   = (float*)d_out;
    float* h_fin = out + (size_t)TSTEPS * NROWS * DOUT;
    float* c_fin = h_fin + (size_t)NROWS * DH;

    static int smem_set = 0;
    if (!smem_set) {
        cudaFuncSetAttribute(lstm_step,
                             cudaFuncAttributeMaxDynamicSharedMemorySize, SMEM_BYTES);
        smem_set = 1;
    }

    detect_mask_kernel<<<1, 32>>>(mask);
    init_state<<<(NROWS * DH / 4) / 256, 256>>>(h0, c0);
    split_weights<<<NCHUNK * 512 * 16 / 256, 256>>>(W_ih, W_hh);
    for (int t = 0; t < TSTEPS; ++t) {
        lstm_step<<<NROWS / MTILE, 256, SMEM_BYTES>>>(
            nodes + (size_t)t * NROWS * 2,
            mask, t,
            W_embed, b_embed, b_ih, b_hh, W_out, b_out,
            out + (size_t)t * NROWS * DOUT,
            h_fin, c_fin,
            (t == TSTEPS - 1) ? 1 : 0);
    }
}